// round 1
// baseline (speedup 1.0000x reference)
#include <cuda_runtime.h>

// ---------------------------------------------------------------------------
// LSTMModel: 4-layer LSTM (H=50) over B=1024, T=512, IN=7, + FC(25) + FC(1).
// Strategy: batch rows are independent through the recurrence -> 128 CTAs x
// 8 rows, no cross-CTA sync; 4 sequential layer kernels; weights held in
// registers (one gate row per thread); h/c/x staged in shared memory.
// ---------------------------------------------------------------------------

#define TT  512
#define BB  1024
#define HH  50
#define GG  200           // 4*H gates
#define NB  8             // batch rows per CTA
#define NCTA (BB / NB)    // 128
#define IN0 7
#define FC1 25

// Scratch: ping-pong sequence buffers [T][B][H] and transposed input [T][B][IN0]
__device__ float g_bufA[TT * BB * HH];
__device__ float g_bufB[TT * BB * HH];
__device__ float g_xT[TT * BB * IN0];

__device__ __forceinline__ float sigmf(float x) {
    // 1/(1+e^-x); overflow-safe: e^-x -> inf => 0
    return __fdividef(1.0f, 1.0f + __expf(-x));
}
__device__ __forceinline__ float tanhfast(float x) {
    // tanh(x) = 1 - 2/(e^{2x}+1); e overflow -> +1, underflow -> -1
    float e = __expf(2.0f * x);
    return 1.0f - __fdividef(2.0f, e + 1.0f);
}

// ---------------------------------------------------------------------------
// Pre-pass: x[b][t][k] -> g_xT[t][b][k]
// ---------------------------------------------------------------------------
__global__ void transpose_x_kernel(const float* __restrict__ x) {
    int idx = blockIdx.x * blockDim.x + threadIdx.x;
    if (idx < BB * TT * IN0) {
        int k = idx % IN0;
        int t = (idx / IN0) % TT;
        int b = idx / (IN0 * TT);
        g_xT[(t * BB + b) * IN0 + k] = x[idx];
    }
}

// ---------------------------------------------------------------------------
// One LSTM layer over the whole sequence for an 8-row batch tile.
// src: 0 -> g_xT, 1 -> g_bufA, 2 -> g_bufB ; dst: 1 -> g_bufA, 2 -> g_bufB
// ---------------------------------------------------------------------------
template <int KIN>
__global__ void __launch_bounds__(256, 1) lstm_layer_kernel(
    int src, int dst,
    const float* __restrict__ Wih,   // [GG][KIN]
    const float* __restrict__ Whh,   // [GG][HH]
    const float* __restrict__ bih,   // [GG]
    const float* __restrict__ bhh)   // [GG]
{
    const float* __restrict__ in_seq =
        (src == 0) ? g_xT : ((src == 1) ? g_bufA : g_bufB);
    float* __restrict__ out_seq = (dst == 1) ? g_bufA : g_bufB;

    __shared__ float sh_h[HH][NB];
    __shared__ float sh_c[HH][NB];
    __shared__ float sh_x[2][KIN][NB];
    __shared__ float sh_g[GG][NB];

    const int tid = threadIdx.x;
    const int b0  = blockIdx.x * NB;
    constexpr int PF = (KIN * NB + 255) / 256;

    // Per-thread weight rows in registers (threads 0..199 own gate rows)
    float wih[KIN], whh[HH];
    float bg = 0.0f;
    if (tid < GG) {
#pragma unroll
        for (int k = 0; k < KIN; k++) wih[k] = Wih[tid * KIN + k];
#pragma unroll
        for (int k = 0; k < HH; k++) whh[k] = Whh[tid * HH + k];
        bg = bih[tid] + bhh[tid];
    }

    // h0 = c0 = 0
    for (int i = tid; i < HH * NB; i += 256) {
        (&sh_h[0][0])[i] = 0.0f;
        (&sh_c[0][0])[i] = 0.0f;
    }
    // stage input for t=0
    for (int i = tid; i < KIN * NB; i += 256) {
        int b = i % NB, k = i / NB;
        sh_x[0][k][b] = in_seq[(0 * BB + b0 + b) * KIN + k];
    }
    __syncthreads();

    int buf = 0;
    for (int t = 0; t < TT; t++) {
        // ---- prefetch next timestep's input into registers (latency overlap)
        float pf[PF];
        const bool has_next = (t + 1 < TT);
        if (has_next) {
#pragma unroll
            for (int j = 0; j < PF; j++) {
                int i = tid + j * 256;
                if (i < KIN * NB) {
                    int b = i % NB, k = i / NB;
                    pf[j] = in_seq[((t + 1) * BB + b0 + b) * KIN + k];
                }
            }
        }

        // ---- gate phase: gates[g][b] = bias + Wih.x + Whh.h
        if (tid < GG) {
            float acc[NB];
#pragma unroll
            for (int b = 0; b < NB; b++) acc[b] = bg;
#pragma unroll
            for (int k = 0; k < KIN; k++) {
                float w = wih[k];
                float4 x0 = *(const float4*)&sh_x[buf][k][0];
                float4 x1 = *(const float4*)&sh_x[buf][k][4];
                acc[0] += w * x0.x; acc[1] += w * x0.y;
                acc[2] += w * x0.z; acc[3] += w * x0.w;
                acc[4] += w * x1.x; acc[5] += w * x1.y;
                acc[6] += w * x1.z; acc[7] += w * x1.w;
            }
#pragma unroll
            for (int k = 0; k < HH; k++) {
                float w = whh[k];
                float4 h0 = *(const float4*)&sh_h[k][0];
                float4 h1 = *(const float4*)&sh_h[k][4];
                acc[0] += w * h0.x; acc[1] += w * h0.y;
                acc[2] += w * h0.z; acc[3] += w * h0.w;
                acc[4] += w * h1.x; acc[5] += w * h1.y;
                acc[6] += w * h1.z; acc[7] += w * h1.w;
            }
#pragma unroll
            for (int b = 0; b < NB; b++) sh_g[tid][b] = acc[b];
        }

        // ---- park prefetched input into the other buffer
        if (has_next) {
#pragma unroll
            for (int j = 0; j < PF; j++) {
                int i = tid + j * 256;
                if (i < KIN * NB) {
                    int b = i % NB, k = i / NB;
                    sh_x[buf ^ 1][k][b] = pf[j];
                }
            }
        }
        __syncthreads();

        // ---- update phase: 200 threads, thread = (unit j, batch pair)
        if (tid < GG) {
            int jj = tid >> 2;
            int bb = (tid & 3) * 2;
#pragma unroll
            for (int q = 0; q < 2; q++) {
                int b = bb + q;
                float ig = sigmf(sh_g[jj][b]);
                float fg = sigmf(sh_g[HH + jj][b]);
                float gg = tanhfast(sh_g[2 * HH + jj][b]);
                float og = sigmf(sh_g[3 * HH + jj][b]);
                float c = fg * sh_c[jj][b] + ig * gg;
                sh_c[jj][b] = c;
                float h = og * tanhfast(c);
                sh_h[jj][b] = h;
                out_seq[(t * BB + b0 + b) * HH + jj] = h;
            }
        }
        buf ^= 1;
        __syncthreads();
    }
}

// ---------------------------------------------------------------------------
// FC head: out[b] = W2 . relu(W1 . h_last[b] + b1) + b2
// ---------------------------------------------------------------------------
__global__ void fc_head_kernel(int src,
                               const float* __restrict__ W1,
                               const float* __restrict__ b1,
                               const float* __restrict__ W2,
                               const float* __restrict__ b2,
                               float* __restrict__ out)
{
    const float* __restrict__ hseq = (src == 1) ? g_bufA : g_bufB;
    __shared__ float sW1[FC1 * HH];
    __shared__ float sW2[FC1];
    __shared__ float sb1[FC1];

    int tid = threadIdx.x;
    for (int i = tid; i < FC1 * HH; i += 256) sW1[i] = W1[i];
    if (tid < FC1) { sW2[tid] = W2[tid]; sb1[tid] = b1[tid]; }
    __syncthreads();

    int b = blockIdx.x * blockDim.x + tid;
    if (b < BB) {
        const float* h = &hseq[((TT - 1) * BB + b) * HH];
        float hreg[HH];
#pragma unroll
        for (int k = 0; k < HH; k++) hreg[k] = h[k];
        float o = b2[0];
#pragma unroll
        for (int j = 0; j < FC1; j++) {
            float a = sb1[j];
#pragma unroll
            for (int k = 0; k < HH; k++) a += sW1[j * HH + k] * hreg[k];
            o += sW2[j] * fmaxf(a, 0.0f);
        }
        out[b] = o;
    }
}

// ---------------------------------------------------------------------------
extern "C" void kernel_launch(void* const* d_in, const int* in_sizes, int n_in,
                              void* d_out, int out_size)
{
    const float* x    = (const float*)d_in[0];
    const float* Wih0 = (const float*)d_in[1];
    const float* Whh0 = (const float*)d_in[2];
    const float* bih0 = (const float*)d_in[3];
    const float* bhh0 = (const float*)d_in[4];
    const float* Wih1 = (const float*)d_in[5];
    const float* Whh1 = (const float*)d_in[6];
    const float* bih1 = (const float*)d_in[7];
    const float* bhh1 = (const float*)d_in[8];
    const float* Wih2 = (const float*)d_in[9];
    const float* Whh2 = (const float*)d_in[10];
    const float* bih2 = (const float*)d_in[11];
    const float* bhh2 = (const float*)d_in[12];
    const float* Wih3 = (const float*)d_in[13];
    const float* Whh3 = (const float*)d_in[14];
    const float* bih3 = (const float*)d_in[15];
    const float* bhh3 = (const float*)d_in[16];
    const float* W1   = (const float*)d_in[17];
    const float* b1   = (const float*)d_in[18];
    const float* W2   = (const float*)d_in[19];
    const float* b2   = (const float*)d_in[20];
    float* out = (float*)d_out;

    // 1) transpose x to [t][b][k]
    {
        int total = BB * TT * IN0;
        int blocks = (total + 255) / 256;
        transpose_x_kernel<<<blocks, 256>>>(x);
    }
    // 2) four LSTM layers (ping-pong buffers)
    lstm_layer_kernel<IN0><<<NCTA, 256>>>(0, 1, Wih0, Whh0, bih0, bhh0);
    lstm_layer_kernel<HH> <<<NCTA, 256>>>(1, 2, Wih1, Whh1, bih1, bhh1);
    lstm_layer_kernel<HH> <<<NCTA, 256>>>(2, 1, Wih2, Whh2, bih2, bhh2);
    lstm_layer_kernel<HH> <<<NCTA, 256>>>(1, 2, Wih3, Whh3, bih3, bhh3);
    // 3) FC head on h at t = T-1 (lives in buffer 2)
    fc_head_kernel<<<(BB + 255) / 256, 256>>>(2, W1, b1, W2, b2, out);
}